// round 4
// baseline (speedup 1.0000x reference)
#include <cuda_runtime.h>
#include <cuda_bf16.h>
#include <cstdint>

// Problem constants
#define B_   8
#define TGT  256
#define SRC  256
#define DM   512
#define LDIM 256            // projection width (== SRC)
#define LOGEPS (-18.420680743952367f)   // log(1e-8)

// -------- scratch (device globals; no allocation) --------
__device__ float g_dt[B_ * TGT * LDIM];   // 2 MB: dec @ W1
__device__ float g_et[B_ * SRC * LDIM];   // 2 MB: enc @ W2

// ---------------- helpers ----------------
__device__ __forceinline__ float tanhapx(float x) {
    float y;
    asm("tanh.approx.f32 %0, %1;" : "=f"(y) : "f"(x));
    return y;
}

__device__ __forceinline__ unsigned long long pk2(float x) {
    unsigned long long r;
    asm("mov.b64 %0, {%1, %1};" : "=l"(r) : "f"(x));
    return r;
}
__device__ __forceinline__ unsigned long long fma2(unsigned long long a,
                                                   unsigned long long b,
                                                   unsigned long long c) {
    unsigned long long d;
    asm("fma.rn.f32x2 %0, %1, %2, %3;" : "=l"(d) : "l"(a), "l"(b), "l"(c));
    return d;
}
__device__ __forceinline__ void unpk2(unsigned long long v, float& lo, float& hi) {
    asm("mov.b64 {%0, %1}, %2;" : "=f"(lo), "=f"(hi) : "l"(v));
}

__device__ __forceinline__ void cp_async16(void* smem_dst, const void* gmem_src) {
    unsigned saddr = (unsigned)__cvta_generic_to_shared(smem_dst);
    asm volatile("cp.async.ca.shared.global [%0], [%1], 16;"
                 :: "r"(saddr), "l"(gmem_src));
}
__device__ __forceinline__ void cp_commit() {
    asm volatile("cp.async.commit_group;" ::: "memory");
}
__device__ __forceinline__ void cp_wait0() {
    asm volatile("cp.async.wait_group 0;" ::: "memory");
}

// =====================================================================
// Kernel A: Y = X @ W.   X: [2048, 512], W: [512, 256], Y: [2048, 256]
// blockIdx.z = 0 -> dec@W1 -> g_dt ; 1 -> enc@W2 -> g_et
// 64x64 tile, BK=16, 256 threads, 4x4 per thread, f32x2 packed FFMA.
// =====================================================================
__global__ __launch_bounds__(256) void gemm64_kernel(
    const float* __restrict__ dec, const float* __restrict__ enc,
    const float* __restrict__ W1,  const float* __restrict__ W2)
{
    const float* X; const float* W; float* Y;
    if (blockIdx.z == 0) { X = dec; W = W1; Y = g_dt; }
    else                 { X = enc; W = W2; Y = g_et; }

    __shared__ float As[16][68];   // [k][m], padded
    __shared__ float Bs[16][68];   // [k][n], padded

    const int tid = threadIdx.x;
    const int tx  = tid & 15;       // n direction (x4)
    const int ty  = tid >> 4;       // m direction (x4)
    const int m0  = blockIdx.y * 64;
    const int n0  = blockIdx.x * 64;

    // global load assignments
    const int la_m = tid >> 2;            // 0..63
    const int la_k = (tid & 3) * 4;       // 0,4,8,12
    const int lb_k = tid >> 4;            // 0..15
    const int lb_n = (tid & 15) * 4;      // 0..60

    const float* Aptr = X + (size_t)(m0 + la_m) * DM + la_k;
    const float* Bptr = W + (size_t)lb_k * LDIM + n0 + lb_n;

    unsigned long long acc[4][2];
#pragma unroll
    for (int i = 0; i < 4; i++) { acc[i][0] = 0ull; acc[i][1] = 0ull; }

#pragma unroll 1
    for (int kt = 0; kt < DM / 16; kt++) {
        float4 a = *(const float4*)Aptr;  Aptr += 16;
        float4 b = *(const float4*)Bptr;  Bptr += 16 * LDIM;
        __syncthreads();
        As[la_k + 0][la_m] = a.x;
        As[la_k + 1][la_m] = a.y;
        As[la_k + 2][la_m] = a.z;
        As[la_k + 3][la_m] = a.w;
        *(float4*)&Bs[lb_k][lb_n] = b;
        __syncthreads();

#pragma unroll
        for (int k = 0; k < 16; k++) {
            float4 av = *(const float4*)&As[k][ty * 4];
            const unsigned long long* bp =
                (const unsigned long long*)&Bs[k][tx * 4];
            unsigned long long b0 = bp[0], b1 = bp[1];
            float am[4] = {av.x, av.y, av.z, av.w};
#pragma unroll
            for (int i = 0; i < 4; i++) {
                unsigned long long ap = pk2(am[i]);
                acc[i][0] = fma2(ap, b0, acc[i][0]);
                acc[i][1] = fma2(ap, b1, acc[i][1]);
            }
        }
    }

#pragma unroll
    for (int i = 0; i < 4; i++) {
        float4 o;
        unpk2(acc[i][0], o.x, o.y);
        unpk2(acc[i][1], o.z, o.w);
        *(float4*)&Y[(size_t)(m0 + ty * 4 + i) * LDIM + n0 + tx * 4] = o;
    }
}

// =====================================================================
// Kernel B: fused scores + mask + log_softmax + transposed write.
// Grid: (TGT/16, B), 256 threads.  Block owns rows t0..t0+15 of batch b.
//   scores[t,s] = sum_l tanh(dt[t,l] + et[s,l]) * vt[l]
// smem (floats):
//   sDt [16][260]      @ 0        (4160)
//   sEt [2][64][260]   @ 4160     (33280)  double-buffered, cp.async
//   sSc [16][257]      @ 37440    (4112)
//   sVt [256]          @ 41552
//   sLse[16]           @ 41808
// total 41824 floats = 167296 B (dynamic)
// =====================================================================
#define OFF_ET  4160
#define OFF_SC  37440
#define OFF_VT  41552
#define OFF_LSE 41808
#define SMEM_B_BYTES (41824 * 4)
#define LPAD 260
#define SPAD 257

__device__ __forceinline__ void load_et_tile(float* dst, const float* src, int tid) {
#pragma unroll
    for (int i = 0; i < 16; i++) {
        int idx = tid + i * 256;          // float4 index 0..4095
        int r = idx >> 6, c = idx & 63;
        cp_async16(&dst[r * LPAD + c * 4], src + r * LDIM + c * 4);
    }
    cp_commit();
}

__global__ __launch_bounds__(256, 1) void attn_kernel(
    const int* __restrict__ lens, const float* __restrict__ vt,
    float* __restrict__ out)
{
    extern __shared__ float sm[];
    float* sDt  = sm;
    float* sEt  = sm + OFF_ET;
    float* sSc  = sm + OFF_SC;
    float* sVt  = sm + OFF_VT;
    float* sLse = sm + OFF_LSE;

    const int tid = threadIdx.x;
    const int b   = blockIdx.y;
    const int t0  = blockIdx.x * 16;

    const float* dtB = g_dt + ((size_t)b * TGT + t0) * LDIM;   // [16][256]
    const float* etB = g_et + (size_t)b * SRC * LDIM;          // [256][256]

    // prefetch et tile 0 (async), then dt tile + vt (sync path)
    load_et_tile(sEt, etB, tid);

#pragma unroll
    for (int i = 0; i < 4; i++) {
        int idx = tid + i * 256;           // float4 index 0..1023
        int r = idx >> 6, c = idx & 63;
        float4 v = ((const float4*)dtB)[idx];
        *(float4*)&sDt[r * LPAD + c * 4] = v;
    }
    if (tid < 64) ((float4*)sVt)[tid] = ((const float4*)vt)[tid];

    cp_wait0();
    __syncthreads();

    const int w    = tid >> 5;
    const int lane = tid & 31;
    const float* dR0 = &sDt[(2 * w) * LPAD];
    const float* dR1 = &sDt[(2 * w + 1) * LPAD];

#pragma unroll 1
    for (int st = 0; st < 4; st++) {
        const float* cur = sEt + (st & 1) * (64 * LPAD);
        if (st < 3)
            load_et_tile(sEt + ((st + 1) & 1) * (64 * LPAD),
                         etB + (st + 1) * 64 * LDIM, tid);

        const float* eR0 = &cur[lane * LPAD];
        const float* eR1 = &cur[(lane + 32) * LPAD];

        float a00 = 0.f, a01 = 0.f, a10 = 0.f, a11 = 0.f;
#pragma unroll 8
        for (int l = 0; l < 256; l += 4) {
            float4 vv = *(const float4*)&sVt[l];
            float4 d0 = *(const float4*)&dR0[l];
            float4 d1 = *(const float4*)&dR1[l];
            float4 e0 = *(const float4*)&eR0[l];
            float4 e1 = *(const float4*)&eR1[l];

            a00 += tanhapx(d0.x + e0.x) * vv.x;
            a01 += tanhapx(d0.x + e1.x) * vv.x;
            a10 += tanhapx(d1.x + e0.x) * vv.x;
            a11 += tanhapx(d1.x + e1.x) * vv.x;

            a00 += tanhapx(d0.y + e0.y) * vv.y;
            a01 += tanhapx(d0.y + e1.y) * vv.y;
            a10 += tanhapx(d1.y + e0.y) * vv.y;
            a11 += tanhapx(d1.y + e1.y) * vv.y;

            a00 += tanhapx(d0.z + e0.z) * vv.z;
            a01 += tanhapx(d0.z + e1.z) * vv.z;
            a10 += tanhapx(d1.z + e0.z) * vv.z;
            a11 += tanhapx(d1.z + e1.z) * vv.z;

            a00 += tanhapx(d0.w + e0.w) * vv.w;
            a01 += tanhapx(d0.w + e1.w) * vv.w;
            a10 += tanhapx(d1.w + e0.w) * vv.w;
            a11 += tanhapx(d1.w + e1.w) * vv.w;
        }

        const int sg = st * 64;
        sSc[(2 * w) * SPAD + sg + lane]          = a00;
        sSc[(2 * w) * SPAD + sg + lane + 32]     = a01;
        sSc[(2 * w + 1) * SPAD + sg + lane]      = a10;
        sSc[(2 * w + 1) * SPAD + sg + lane + 32] = a11;

        if (st < 3) cp_wait0();
        __syncthreads();
    }

    // ---- masked log_softmax over s, per t-row ----
    const int len = lens[b];

#pragma unroll
    for (int r = 0; r < 2; r++) {
        const int lt = 2 * w + r;
        float v[8];
        float mx = -3.0e38f;
#pragma unroll
        for (int i = 0; i < 8; i++) {
            int s = lane + 32 * i;
            float x = sSc[lt * SPAD + s];
            if (s >= len) x += LOGEPS;
            v[i] = x;
            mx = fmaxf(mx, x);
        }
#pragma unroll
        for (int o = 16; o > 0; o >>= 1)
            mx = fmaxf(mx, __shfl_xor_sync(0xffffffffu, mx, o));
        float sum = 0.f;
#pragma unroll
        for (int i = 0; i < 8; i++) sum += __expf(v[i] - mx);
#pragma unroll
        for (int o = 16; o > 0; o >>= 1)
            sum += __shfl_xor_sync(0xffffffffu, sum, o);
        if (lane == 0) sLse[lt] = mx + __logf(sum);
    }
    __syncthreads();

    // ---- transposed, coalesced write: out[b][s][t0+lt] ----
    float* outB = out + (size_t)b * SRC * TGT + t0;
    const int lt = tid & 15;
    const int sB = tid >> 4;
    const float lse = sLse[lt];
#pragma unroll
    for (int p = 0; p < 16; p++) {
        int s = sB + p * 16;
        float x = sSc[lt * SPAD + s];
        if (s >= len) x += LOGEPS;
        outB[(size_t)s * TGT + lt] = x - lse;
    }
}

// =====================================================================
// launcher
// =====================================================================
extern "C" void kernel_launch(void* const* d_in, const int* in_sizes, int n_in,
                              void* d_out, int out_size)
{
    const float* dec = (const float*)d_in[0];   // [8,256,512]
    const float* enc = (const float*)d_in[1];   // [8,256,512]
    const int*   len = (const int*)  d_in[2];   // [8]
    const float* W1  = (const float*)d_in[3];   // [512,256]
    const float* W2  = (const float*)d_in[4];   // [512,256]
    const float* vt  = (const float*)d_in[5];   // [256]
    float* out = (float*)d_out;                 // [8,256,256] = [b][s][t]

    (void)in_sizes; (void)n_in; (void)out_size;

    cudaFuncSetAttribute(attn_kernel,
                         cudaFuncAttributeMaxDynamicSharedMemorySize,
                         SMEM_B_BYTES);

    dim3 gGemm(LDIM / 64, (B_ * TGT) / 64, 2);   // (4, 32, 2)
    gemm64_kernel<<<gGemm, 256>>>(dec, enc, W1, W2);

    dim3 gAttn(TGT / 16, B_);                    // (16, 8)
    attn_kernel<<<gAttn, 256, SMEM_B_BYTES>>>(len, vt, out);
}